// round 4
// baseline (speedup 1.0000x reference)
#include <cuda_runtime.h>
#include <cstdint>

#define NCOL 65536
#define NB 32
#define NPTS 2048

#define OFF1 0
#define OFF2 64
#define OFF3 192
#define OFFH1 1216
#define OFFH2 1728
#define OFFH3 1984
#define NSTAT 2112

// ---- scratch (transposed layout: [col][channel], channel contiguous) ----
__device__ float d_raw1[(size_t)NCOL * 64];
__device__ float d_raw2[(size_t)NCOL * 128];
__device__ float d_rawh1[(size_t)NCOL * 512];
__device__ float d_rawh2[(size_t)NCOL * 256];
__device__ float d_rawh3[(size_t)NCOL * 128];
__device__ float d_sum[NSTAT];
__device__ float d_sq[NSTAT];
__device__ float d_scale[NSTAT];
__device__ float d_shift[NSTAT];
__device__ unsigned d_gmax[NB * 1024];
__device__ float d_gbn[NB * 1024];
__device__ float d_hvec[NB * 512];
__device__ int d_nv[NB];

__device__ __forceinline__ float to_tf32(float x) {
    uint32_t u;
    asm("cvt.rna.tf32.f32 %0, %1;" : "=r"(u) : "f"(x));
    return __uint_as_float(u);
}
__device__ __forceinline__ void mma8(float c[4], uint32_t a0, uint32_t a1, uint32_t a2,
                                     uint32_t a3, uint32_t b0, uint32_t b1) {
    asm volatile(
        "mma.sync.aligned.m16n8k8.row.col.f32.tf32.tf32.f32 "
        "{%0,%1,%2,%3}, {%4,%5,%6,%7}, {%8,%9}, {%0,%1,%2,%3};"
        : "+f"(c[0]), "+f"(c[1]), "+f"(c[2]), "+f"(c[3])
        : "r"(a0), "r"(a1), "r"(a2), "r"(a3), "r"(b0), "r"(b1));
}

// ================= small kernels =================
__global__ void zero_kernel() {
    int i = blockIdx.x * 256 + threadIdx.x;
    if (i < NSTAT) { d_sum[i] = 0.f; d_sq[i] = 0.f; }
    if (i < NB * 1024) d_gmax[i] = 0u;
    if (i < NB) d_nv[i] = 0;
}

// conv1: 3 -> 64, transposed out [col][64], fused stats
__global__ void conv1_kernel(const float* __restrict__ pts,
                             const float* __restrict__ w,
                             const float* __restrict__ b) {
    __shared__ float ws[192], bs[64], bsum[64], bsq[64];
    int tid = threadIdx.x;
    if (tid < 192) ws[tid] = w[tid];
    if (tid < 64) { bs[tid] = b[tid]; bsum[tid] = 0.f; bsq[tid] = 0.f; }
    __syncthreads();
    int wid = tid >> 5, lid = tid & 31;
    int colbase = (blockIdx.x * 8 + wid) * 32;
    int bb = colbase >> 11, n = colbase & 2047;
    const float* p = pts + (size_t)bb * 3 * NPTS + n + lid;
    float p0 = p[0], p1 = p[NPTS], p2 = p[2 * NPTS];
    float wa0 = ws[lid * 3], wa1 = ws[lid * 3 + 1], wa2 = ws[lid * 3 + 2];
    float wb0 = ws[(lid + 32) * 3], wb1 = ws[(lid + 32) * 3 + 1], wb2 = ws[(lid + 32) * 3 + 2];
    float ba = bs[lid], bbv = bs[lid + 32];
    float sa = 0.f, qa = 0.f, sb = 0.f, qb = 0.f;
#pragma unroll 8
    for (int c = 0; c < 32; c++) {
        float x = __shfl_sync(0xffffffffu, p0, c);
        float y = __shfl_sync(0xffffffffu, p1, c);
        float z = __shfl_sync(0xffffffffu, p2, c);
        float va = fmaf(wa0, x, fmaf(wa1, y, fmaf(wa2, z, ba)));
        float vb = fmaf(wb0, x, fmaf(wb1, y, fmaf(wb2, z, bbv)));
        d_raw1[(size_t)(colbase + c) * 64 + lid] = va;
        d_raw1[(size_t)(colbase + c) * 64 + 32 + lid] = vb;
        sa += va; qa = fmaf(va, va, qa);
        sb += vb; qb = fmaf(vb, vb, qb);
    }
    atomicAdd(&bsum[lid], sa); atomicAdd(&bsq[lid], qa);
    atomicAdd(&bsum[32 + lid], sb); atomicAdd(&bsq[32 + lid], qb);
    __syncthreads();
    if (tid < 64) {
        atomicAdd(&d_sum[OFF1 + tid], bsum[tid]);
        atomicAdd(&d_sq[OFF1 + tid], bsq[tid]);
    }
}

__global__ void finalize_kernel(int C, int off, const float* __restrict__ g,
                                const float* __restrict__ be) {
    int c = blockIdx.x * 128 + threadIdx.x;
    if (c >= C) return;
    float m = d_sum[off + c] * (1.0f / NCOL);
    float v = d_sq[off + c] * (1.0f / NCOL) - m * m;
    float sc = g[c] * rsqrtf(v + 1e-5f);
    d_scale[off + c] = sc;
    d_shift[off + c] = fmaf(-m, sc, be[c]);
}

// ================= 3xTF32 HMMA GEMM (fp32-accurate) =================
// smem (floats): As_hi@0 [128][20], As_lo@2560, Xs_hi@5120, Xs_lo@7680,
//                S[64][132] overlays @0, sc@10240, sh@10752 (11264 fl = 45056 B)
template <bool STORE, bool DOMAX, bool COLBIAS>
__global__ void __launch_bounds__(256, 2) mma_kernel(
    const float* __restrict__ W, int lda, int woff, const float* __restrict__ bias,
    const float* __restrict__ Xraw, int Cin, int actoff,
    float* __restrict__ Y, int statoff, int Mtot,
    const float* __restrict__ colbias) {
    __shared__ float sm[11264];
    float* Ah = sm;
    float* Al = sm + 2560;
    float* Xh = sm + 5120;
    float* Xl = sm + 7680;
    float* S = sm;
    float* sc_s = sm + 10240;
    float* sh_s = sm + 10752;

    const int tid = threadIdx.x;
    const int wid = tid >> 5, lane = tid & 31;
    const int g = lane >> 2, t = lane & 3;
    const int m0 = (wid & 3) * 32;
    const int n0 = (wid >> 2) * 64;
    const int col0 = blockIdx.x * 128;
    const int bb = col0 >> 11;

    for (int k = tid; k < Cin; k += 256) {
        sc_s[k] = d_scale[actoff + k];
        sh_s[k] = d_shift[actoff + k];
    }

    const int row = tid >> 1;
    const int cg = (tid & 1) * 8;
    const int nkc = Cin >> 4;
    const int MC = Mtot >> 7;

    for (int mc = 0; mc < MC; mc++) {
        float c[2][8][4];
#pragma unroll
        for (int i = 0; i < 2; i++)
#pragma unroll
            for (int j = 0; j < 8; j++)
#pragma unroll
                for (int k = 0; k < 4; k++) c[i][j][k] = 0.f;

        const float* Wm = W + (size_t)(mc * 128 + row) * lda + woff + cg;
        const float* Xc = Xraw + (size_t)(col0 + row) * Cin + cg;

        float4 pa0 = *(const float4*)(Wm);
        float4 pa1 = *(const float4*)(Wm + 4);
        float4 px0 = *(const float4*)(Xc);
        float4 px1 = *(const float4*)(Xc + 4);

        for (int kc = 0; kc < nkc; kc++) {
            __syncthreads();
            // STS A split (hi/lo)
            {
                float* adh = Ah + row * 20 + cg;
                float* adl = Al + row * 20 + cg;
                float v[8] = {pa0.x, pa0.y, pa0.z, pa0.w, pa1.x, pa1.y, pa1.z, pa1.w};
#pragma unroll
                for (int e = 0; e < 8; e++) {
                    float h = to_tf32(v[e]);
                    adh[e] = h;
                    adl[e] = to_tf32(v[e] - h);
                }
            }
            // STS X split (BN + ReLU first, then hi/lo)
            {
                const int kb = kc * 16 + cg;
                float* xdh = Xh + row * 20 + cg;
                float* xdl = Xl + row * 20 + cg;
                float v[8] = {px0.x, px0.y, px0.z, px0.w, px1.x, px1.y, px1.z, px1.w};
#pragma unroll
                for (int e = 0; e < 8; e++) {
                    float a = fmaxf(fmaf(sc_s[kb + e], v[e], sh_s[kb + e]), 0.f);
                    float h = to_tf32(a);
                    xdh[e] = h;
                    xdl[e] = to_tf32(a - h);
                }
            }
            __syncthreads();
            if (kc + 1 < nkc) {
                pa0 = *(const float4*)(Wm + (kc + 1) * 16);
                pa1 = *(const float4*)(Wm + (kc + 1) * 16 + 4);
                px0 = *(const float4*)(Xc + (kc + 1) * 16);
                px1 = *(const float4*)(Xc + (kc + 1) * 16 + 4);
            }
#pragma unroll
            for (int kk = 0; kk < 2; kk++) {
                const int kb = kk * 8;
                uint32_t ah[2][4], al[2][4];
#pragma unroll
                for (int i = 0; i < 2; i++) {
                    const int ao = (m0 + i * 16 + g) * 20 + kb + t;
                    ah[i][0] = __float_as_uint(Ah[ao]);
                    ah[i][1] = __float_as_uint(Ah[ao + 160]);
                    ah[i][2] = __float_as_uint(Ah[ao + 4]);
                    ah[i][3] = __float_as_uint(Ah[ao + 164]);
                    al[i][0] = __float_as_uint(Al[ao]);
                    al[i][1] = __float_as_uint(Al[ao + 160]);
                    al[i][2] = __float_as_uint(Al[ao + 4]);
                    al[i][3] = __float_as_uint(Al[ao + 164]);
                }
#pragma unroll
                for (int j = 0; j < 8; j++) {
                    const int bo = (n0 + j * 8 + g) * 20 + kb + t;
                    uint32_t b0h = __float_as_uint(Xh[bo]);
                    uint32_t b1h = __float_as_uint(Xh[bo + 4]);
                    uint32_t b0l = __float_as_uint(Xl[bo]);
                    uint32_t b1l = __float_as_uint(Xl[bo + 4]);
#pragma unroll
                    for (int i = 0; i < 2; i++) {
                        mma8(c[i][j], ah[i][0], ah[i][1], ah[i][2], ah[i][3], b0l, b1l);
                        mma8(c[i][j], al[i][0], al[i][1], al[i][2], al[i][3], b0h, b1h);
                        mma8(c[i][j], ah[i][0], ah[i][1], ah[i][2], ah[i][3], b0h, b1h);
                    }
                }
            }
        }

        // ---- epilogue: bias, stats (+max), optional transposed store ----
#pragma unroll
        for (int i = 0; i < 2; i++) {
            const int chA = mc * 128 + m0 + i * 16 + g;
            const int chB = chA + 8;
            const float bvA = COLBIAS ? colbias[bb * Mtot + chA] : bias[chA];
            const float bvB = COLBIAS ? colbias[bb * Mtot + chB] : bias[chB];
            float sA = 0.f, qA = 0.f, sB = 0.f, qB = 0.f;
            float mA = -3.4e38f, mB = -3.4e38f;
#pragma unroll
            for (int j = 0; j < 8; j++) {
                c[i][j][0] += bvA; c[i][j][1] += bvA;
                c[i][j][2] += bvB; c[i][j][3] += bvB;
                sA += c[i][j][0] + c[i][j][1];
                qA = fmaf(c[i][j][0], c[i][j][0], qA);
                qA = fmaf(c[i][j][1], c[i][j][1], qA);
                sB += c[i][j][2] + c[i][j][3];
                qB = fmaf(c[i][j][2], c[i][j][2], qB);
                qB = fmaf(c[i][j][3], c[i][j][3], qB);
                if (DOMAX) {
                    mA = fmaxf(mA, fmaxf(c[i][j][0], c[i][j][1]));
                    mB = fmaxf(mB, fmaxf(c[i][j][2], c[i][j][3]));
                }
            }
#pragma unroll
            for (int o = 1; o <= 2; o <<= 1) {
                sA += __shfl_xor_sync(0xffffffffu, sA, o);
                qA += __shfl_xor_sync(0xffffffffu, qA, o);
                sB += __shfl_xor_sync(0xffffffffu, sB, o);
                qB += __shfl_xor_sync(0xffffffffu, qB, o);
                if (DOMAX) {
                    mA = fmaxf(mA, __shfl_xor_sync(0xffffffffu, mA, o));
                    mB = fmaxf(mB, __shfl_xor_sync(0xffffffffu, mB, o));
                }
            }
            if (t == 0) {
                atomicAdd(&d_sum[statoff + chA], sA);
                atomicAdd(&d_sq[statoff + chA], qA);
                atomicAdd(&d_sum[statoff + chB], sB);
                atomicAdd(&d_sq[statoff + chB], qB);
                if (DOMAX) {
                    unsigned uA = __float_as_uint(mA);
                    uA = (uA >> 31) ? ~uA : (uA | 0x80000000u);
                    atomicMax(&d_gmax[bb * Mtot + chA], uA);
                    unsigned uB = __float_as_uint(mB);
                    uB = (uB >> 31) ? ~uB : (uB | 0x80000000u);
                    atomicMax(&d_gmax[bb * Mtot + chB], uB);
                }
            }
        }

        if (STORE) {
#pragma unroll
            for (int h = 0; h < 2; h++) {
                __syncthreads();
                if ((wid >> 2) == h) {
#pragma unroll
                    for (int i = 0; i < 2; i++)
#pragma unroll
                        for (int j = 0; j < 8; j++) {
                            const int lc = j * 8 + t * 2;
                            const int chl = m0 + i * 16 + g;
                            S[lc * 132 + chl] = c[i][j][0];
                            S[(lc + 1) * 132 + chl] = c[i][j][1];
                            S[lc * 132 + chl + 8] = c[i][j][2];
                            S[(lc + 1) * 132 + chl + 8] = c[i][j][3];
                        }
                }
                __syncthreads();
                const int lcol = tid >> 2;
                const int cg2 = (tid & 3) * 32;
                float* yp = Y + (size_t)(col0 + h * 64 + lcol) * Mtot + mc * 128 + cg2;
                const float* sp = S + lcol * 132 + cg2;
#pragma unroll
                for (int q = 0; q < 8; q++)
                    *(float4*)(yp + q * 4) = *(const float4*)(sp + q * 4);
            }
        }
    }
}

// decode max, apply conv3 BN affine
__global__ void gbn_kernel() {
    int i = blockIdx.x * 256 + threadIdx.x;
    unsigned u = d_gmax[i];
    float f = (u >> 31) ? __uint_as_float(u & 0x7FFFFFFFu) : __uint_as_float(~u);
    int c = i & 1023;
    d_gbn[i] = fmaf(d_scale[OFF3 + c], f, d_shift[OFF3 + c]);
}

// hvec[b][oc] = h_w1[oc, :1024] @ g_bn[b] + h_b1[oc]
__global__ void hvec_kernel(const float* __restrict__ w1, const float* __restrict__ b1) {
    int bbk = blockIdx.x;
    int oc = blockIdx.y * 128 + threadIdx.x;
    __shared__ float gb[1024];
    for (int i = threadIdx.x; i < 1024; i += 128) gb[i] = d_gbn[bbk * 1024 + i];
    __syncthreads();
    float a = b1[oc];
    const float* wr = w1 + (size_t)oc * 1088;
#pragma unroll 4
    for (int k = 0; k < 1024; k++) a = fmaf(wr[k], gb[k], a);
    d_hvec[bbk * 512 + oc] = a;
}

// h4: 128 -> 1, warp per column ([col][128] layout), weights into d_out
__global__ void h4_kernel(const float* __restrict__ w4, const float* __restrict__ b4,
                          float* __restrict__ out) {
    __shared__ float ws[128], scs[128], shs[128];
    __shared__ int vcnt;
    int tid = threadIdx.x;
    if (tid < 128) {
        ws[tid] = w4[tid];
        scs[tid] = d_scale[OFFH3 + tid];
        shs[tid] = d_shift[OFFH3 + tid];
    }
    if (tid == 0) vcnt = 0;
    __syncthreads();
    int wid = tid >> 5, lid = tid & 31;
    int col = blockIdx.x * 8 + wid;
    const float* src = d_rawh3 + (size_t)col * 128;
    float a = 0.f;
#pragma unroll
    for (int c = 0; c < 4; c++) {
        int k = c * 32 + lid;
        float v = src[k];
        a = fmaf(ws[k], fmaxf(fmaf(scs[k], v, shs[k]), 0.f), a);
    }
#pragma unroll
    for (int o = 16; o >= 1; o >>= 1) a += __shfl_xor_sync(0xffffffffu, a, o);
    if (lid == 0) {
        float wv = 1.f + a + __ldg(b4);
        out[96 + col] = wv;
        if (wv > 1e-4f) atomicAdd(&vcnt, 1);
    }
    __syncthreads();
    if (tid == 0) atomicAdd(&d_nv[(blockIdx.x * 8) >> 11], vcnt);
}

// per-batch weighted 3x3 normal equations + Cholesky
__global__ void solve_kernel(const float* __restrict__ pts, float* __restrict__ out) {
    int bbk = blockIdx.x;
    const float* w = out + 96 + bbk * NPTS;
    const float* px = pts + (size_t)bbk * 3 * NPTS;
    bool usew = d_nv[bbk] > 3;
    float acc[9];
#pragma unroll
    for (int k = 0; k < 9; k++) acc[k] = 0.f;
    for (int n = threadIdx.x; n < NPTS; n += 256) {
        float wv = w[n];
        float we = usew ? ((wv > 1e-4f) ? wv : 0.f) : 1.f;
        float x = px[n], y = px[NPTS + n], z = px[2 * NPTS + n];
        acc[0] = fmaf(we * x, x, acc[0]);
        acc[1] = fmaf(we * x, y, acc[1]);
        acc[2] += we * x;
        acc[3] = fmaf(we * y, y, acc[3]);
        acc[4] += we * y;
        acc[5] += we;
        acc[6] = fmaf(we * x, z, acc[6]);
        acc[7] = fmaf(we * y, z, acc[7]);
        acc[8] = fmaf(we, z, acc[8]);
    }
#pragma unroll
    for (int k = 0; k < 9; k++)
#pragma unroll
        for (int o = 16; o >= 1; o >>= 1) acc[k] += __shfl_xor_sync(0xffffffffu, acc[k], o);
    __shared__ float red[8][9];
    int wid = threadIdx.x >> 5, lane = threadIdx.x & 31;
    if (lane == 0)
        for (int k = 0; k < 9; k++) red[wid][k] = acc[k];
    __syncthreads();
    if (threadIdx.x == 0) {
        float a[9];
        for (int k = 0; k < 9; k++) {
            float s = 0.f;
            for (int i = 0; i < 8; i++) s += red[i][k];
            a[k] = s;
        }
        float L11 = sqrtf(a[0]);
        float L21 = a[1] / L11, L31 = a[2] / L11;
        float L22 = sqrtf(a[3] - L21 * L21);
        float L32 = (a[4] - L31 * L21) / L22;
        float L33 = sqrtf(a[5] - L31 * L31 - L32 * L32);
        float y1 = a[6] / L11;
        float y2 = (a[7] - L21 * y1) / L22;
        float y3 = (a[8] - L31 * y1 - L32 * y2) / L33;
        float be3 = y3 / L33;
        float be2 = (y2 - L32 * be3) / L22;
        float be1 = (y1 - L21 * be2 - L31 * be3) / L11;
        out[bbk * 3 + 0] = be1;
        out[bbk * 3 + 1] = be2;
        out[bbk * 3 + 2] = be3;
    }
}

// ================= launch =================
extern "C" void kernel_launch(void* const* d_in, const int* in_sizes, int n_in,
                              void* d_out, int out_size) {
    const float* pts = (const float*)d_in[0];
    const float* e_w1 = (const float*)d_in[1];
    const float* e_b1 = (const float*)d_in[2];
    const float* e_g1 = (const float*)d_in[3];
    const float* e_be1 = (const float*)d_in[4];
    const float* e_w2 = (const float*)d_in[5];
    const float* e_b2 = (const float*)d_in[6];
    const float* e_g2 = (const float*)d_in[7];
    const float* e_be2 = (const float*)d_in[8];
    const float* e_w3 = (const float*)d_in[9];
    const float* e_b3 = (const float*)d_in[10];
    const float* e_g3 = (const float*)d_in[11];
    const float* e_be3 = (const float*)d_in[12];
    const float* h_w1 = (const float*)d_in[13];
    const float* h_b1 = (const float*)d_in[14];
    const float* h_g1 = (const float*)d_in[15];
    const float* h_be1 = (const float*)d_in[16];
    const float* h_w2 = (const float*)d_in[17];
    const float* h_b2 = (const float*)d_in[18];
    const float* h_g2 = (const float*)d_in[19];
    const float* h_be2 = (const float*)d_in[20];
    const float* h_w3 = (const float*)d_in[21];
    const float* h_b3 = (const float*)d_in[22];
    const float* h_g3 = (const float*)d_in[23];
    const float* h_be3 = (const float*)d_in[24];
    const float* h_w4 = (const float*)d_in[25];
    const float* h_b4 = (const float*)d_in[26];
    float* out = (float*)d_out;

    float *p_raw1, *p_raw2, *p_rawh1, *p_rawh2, *p_rawh3, *p_hvec;
    cudaGetSymbolAddress((void**)&p_raw1, d_raw1);
    cudaGetSymbolAddress((void**)&p_raw2, d_raw2);
    cudaGetSymbolAddress((void**)&p_rawh1, d_rawh1);
    cudaGetSymbolAddress((void**)&p_rawh2, d_rawh2);
    cudaGetSymbolAddress((void**)&p_rawh3, d_rawh3);
    cudaGetSymbolAddress((void**)&p_hvec, d_hvec);

    zero_kernel<<<128, 256>>>();
    conv1_kernel<<<256, 256>>>(pts, e_w1, e_b1);
    finalize_kernel<<<1, 128>>>(64, OFF1, e_g1, e_be1);
    // conv2: 128 x 65536 x 64
    mma_kernel<true, false, false><<<512, 256>>>(e_w2, 64, 0, e_b2, p_raw1, 64, OFF1,
                                                 p_raw2, OFF2, 128, nullptr);
    finalize_kernel<<<1, 128>>>(128, OFF2, e_g2, e_be2);
    // conv3: 1024 x 65536 x 128 (stats + max only, no store)
    mma_kernel<false, true, false><<<512, 256>>>(e_w3, 128, 0, e_b3, p_raw2, 128, OFF2,
                                                 nullptr, OFF3, 1024, nullptr);
    finalize_kernel<<<8, 128>>>(1024, OFF3, e_g3, e_be3);
    gbn_kernel<<<128, 256>>>();
    hvec_kernel<<<dim3(32, 4), 128>>>(h_w1, h_b1);
    // h1 (pointfeat part): 512 x 65536 x 64, per-batch colbias
    mma_kernel<true, false, true><<<512, 256>>>(h_w1, 1088, 1024, h_b1, p_raw1, 64, OFF1,
                                                p_rawh1, OFFH1, 512, p_hvec);
    finalize_kernel<<<4, 128>>>(512, OFFH1, h_g1, h_be1);
    // h2: 256 x 65536 x 512
    mma_kernel<true, false, false><<<512, 256>>>(h_w2, 512, 0, h_b2, p_rawh1, 512, OFFH1,
                                                 p_rawh2, OFFH2, 256, nullptr);
    finalize_kernel<<<2, 128>>>(256, OFFH2, h_g2, h_be2);
    // h3: 128 x 65536 x 256
    mma_kernel<true, false, false><<<512, 256>>>(h_w3, 256, 0, h_b3, p_rawh2, 256, OFFH2,
                                                 p_rawh3, OFFH3, 128, nullptr);
    finalize_kernel<<<1, 128>>>(128, OFFH3, h_g3, h_be3);
    h4_kernel<<<8192, 256>>>(h_w4, h_b4, out);
    solve_kernel<<<32, 256>>>(pts, out);
}

// round 5
// speedup vs baseline: 1.2614x; 1.2614x over previous
#include <cuda_runtime.h>
#include <cuda_bf16.h>
#include <cstdint>

#define NCOL 65536
#define NB 32
#define NPTS 2048

#define OFF1 0
#define OFF2 64
#define OFF3 192
#define OFFH1 1216
#define OFFH2 1728
#define OFFH3 1984
#define NSTAT 2112

// ---- scratch (transposed layout: [col][channel], channel contiguous) ----
__device__ float d_raw1[(size_t)NCOL * 64];
__device__ float d_raw2[(size_t)NCOL * 128];
__device__ float d_rawh1[(size_t)NCOL * 512];
__device__ float d_rawh2[(size_t)NCOL * 256];
__device__ float d_rawh3[(size_t)NCOL * 128];
__device__ float d_sum[NSTAT];
__device__ float d_sq[NSTAT];
__device__ float d_scale[NSTAT];
__device__ float d_shift[NSTAT];
__device__ unsigned d_gmax[NB * 1024];
__device__ float d_gbn[NB * 1024];
__device__ float d_hvec[NB * 512];
__device__ int d_nv[NB];

__device__ __forceinline__ void mma16(float c[4], const uint32_t a[4], uint32_t b0,
                                      uint32_t b1) {
    asm volatile(
        "mma.sync.aligned.m16n8k16.row.col.f32.bf16.bf16.f32 "
        "{%0,%1,%2,%3}, {%4,%5,%6,%7}, {%8,%9}, {%0,%1,%2,%3};"
        : "+f"(c[0]), "+f"(c[1]), "+f"(c[2]), "+f"(c[3])
        : "r"(a[0]), "r"(a[1]), "r"(a[2]), "r"(a[3]), "r"(b0), "r"(b1));
}
// pack two floats (even k -> low half) as bf16x2
__device__ __forceinline__ uint32_t packb(float lo_e, float hi_e) {
    __nv_bfloat162 h;
    h.x = __float2bfloat16_rn(lo_e);
    h.y = __float2bfloat16_rn(hi_e);
    return *(uint32_t*)&h;
}

// ================= small kernels =================
__global__ void zero_kernel() {
    int i = blockIdx.x * 256 + threadIdx.x;
    if (i < NSTAT) { d_sum[i] = 0.f; d_sq[i] = 0.f; }
    if (i < NB * 1024) d_gmax[i] = 0u;
    if (i < NB) d_nv[i] = 0;
}

// conv1: 3 -> 64, transposed out [col][64], fused stats
__global__ void conv1_kernel(const float* __restrict__ pts,
                             const float* __restrict__ w,
                             const float* __restrict__ b) {
    __shared__ float ws[192], bs[64], bsum[64], bsq[64];
    int tid = threadIdx.x;
    if (tid < 192) ws[tid] = w[tid];
    if (tid < 64) { bs[tid] = b[tid]; bsum[tid] = 0.f; bsq[tid] = 0.f; }
    __syncthreads();
    int wid = tid >> 5, lid = tid & 31;
    int colbase = (blockIdx.x * 8 + wid) * 32;
    int bb = colbase >> 11, n = colbase & 2047;
    const float* p = pts + (size_t)bb * 3 * NPTS + n + lid;
    float p0 = p[0], p1 = p[NPTS], p2 = p[2 * NPTS];
    float wa0 = ws[lid * 3], wa1 = ws[lid * 3 + 1], wa2 = ws[lid * 3 + 2];
    float wb0 = ws[(lid + 32) * 3], wb1 = ws[(lid + 32) * 3 + 1], wb2 = ws[(lid + 32) * 3 + 2];
    float ba = bs[lid], bbv = bs[lid + 32];
    float sa = 0.f, qa = 0.f, sb = 0.f, qb = 0.f;
#pragma unroll 8
    for (int c = 0; c < 32; c++) {
        float x = __shfl_sync(0xffffffffu, p0, c);
        float y = __shfl_sync(0xffffffffu, p1, c);
        float z = __shfl_sync(0xffffffffu, p2, c);
        float va = fmaf(wa0, x, fmaf(wa1, y, fmaf(wa2, z, ba)));
        float vb = fmaf(wb0, x, fmaf(wb1, y, fmaf(wb2, z, bbv)));
        d_raw1[(size_t)(colbase + c) * 64 + lid] = va;
        d_raw1[(size_t)(colbase + c) * 64 + 32 + lid] = vb;
        sa += va; qa = fmaf(va, va, qa);
        sb += vb; qb = fmaf(vb, vb, qb);
    }
    atomicAdd(&bsum[lid], sa); atomicAdd(&bsq[lid], qa);
    atomicAdd(&bsum[32 + lid], sb); atomicAdd(&bsq[32 + lid], qb);
    __syncthreads();
    if (tid < 64) {
        atomicAdd(&d_sum[OFF1 + tid], bsum[tid]);
        atomicAdd(&d_sq[OFF1 + tid], bsq[tid]);
    }
}

__global__ void finalize_kernel(int C, int off, const float* __restrict__ g,
                                const float* __restrict__ be) {
    int c = blockIdx.x * 128 + threadIdx.x;
    if (c >= C) return;
    float m = d_sum[off + c] * (1.0f / NCOL);
    float v = d_sq[off + c] * (1.0f / NCOL) - m * m;
    float sc = g[c] * rsqrtf(v + 1e-5f);
    d_scale[off + c] = sc;
    d_shift[off + c] = fmaf(-m, sc, be[c]);
}

// ================= bf16x3 HMMA GEMM (near-fp32) =================
// K-chunk = 32 (two k16 sub-steps). Fragment-native smem planes, each
// [2(kk)][128(row)][32B], XOR-16 swizzle on bit2 of row, conflict-free.
// byte map: Ah@0 (8KB), Al@8192, Xh@16384, Xl@24576 (32KB total)
// S (store transpose) overlays @0: 64*132 floats = 33792B
// sc@33792 (2KB), sh@35840 (2KB) -> total 37888 B
#define SM_AL 8192
#define SM_XH 16384
#define SM_XL 24576

template <bool STORE, bool DOMAX, bool COLBIAS>
__global__ void __launch_bounds__(256, 2) mma_kernel(
    const float* __restrict__ W, int lda, int woff, const float* __restrict__ bias,
    const float* __restrict__ Xraw, int Cin, int actoff,
    float* __restrict__ Y, int statoff, int Mtot,
    const float* __restrict__ colbias) {
    __shared__ __align__(16) char smem[37888];
    float* S = (float*)smem;
    float* sc_s = (float*)(smem + 33792);
    float* sh_s = (float*)(smem + 35840);

    const int tid = threadIdx.x;
    const int wid = tid >> 5, lane = tid & 31;
    const int g = lane >> 2, t = lane & 3;
    const int m0 = (wid & 3) * 32;
    const int n0 = (wid >> 2) * 64;
    const int col0 = blockIdx.x * 128;
    const int bb = col0 >> 11;

    for (int k = tid; k < Cin; k += 256) {
        sc_s[k] = d_scale[actoff + k];
        sh_s[k] = d_shift[actoff + k];
    }

    // writer role: one 16-k half-row per thread for A and for X
    const int wrow = tid & 127;
    const int wh = tid >> 7;  // which k16 of the 32-chunk
    const uint32_t wswz = ((wrow >> 2) & 1) * 16;
    const uint32_t wbase = (uint32_t)wh * 4096 + (uint32_t)wrow * 32;

    const int nkc = Cin >> 5;
    const int MC = Mtot >> 7;

    for (int mc = 0; mc < MC; mc++) {
        float c[2][8][4];
#pragma unroll
        for (int i = 0; i < 2; i++)
#pragma unroll
            for (int j = 0; j < 8; j++)
#pragma unroll
                for (int k = 0; k < 4; k++) c[i][j][k] = 0.f;

        const float* Wm = W + (size_t)(mc * 128 + wrow) * lda + woff + wh * 16;
        const float* Xc = Xraw + (size_t)(col0 + wrow) * Cin + wh * 16;

        float4 pa[4], px[4];
#pragma unroll
        for (int q = 0; q < 4; q++) {
            pa[q] = *(const float4*)(Wm + q * 4);
            px[q] = *(const float4*)(Xc + q * 4);
        }

        for (int kc = 0; kc < nkc; kc++) {
            __syncthreads();  // consumers (and S-epilogue) done with smem
            // ---- writer: A (raw weights, split hi/lo) ----
            {
                float v[16];
#pragma unroll
                for (int q = 0; q < 4; q++) {
                    v[q * 4 + 0] = pa[q].x; v[q * 4 + 1] = pa[q].y;
                    v[q * 4 + 2] = pa[q].z; v[q * 4 + 3] = pa[q].w;
                }
                uint32_t hw[8], lw[8];
#pragma unroll
                for (int tt = 0; tt < 4; tt++) {
                    float v0 = v[2 * tt], v1 = v[2 * tt + 1];
                    float v8 = v[2 * tt + 8], v9 = v[2 * tt + 9];
                    float h0 = __bfloat162float(__float2bfloat16_rn(v0));
                    float h1 = __bfloat162float(__float2bfloat16_rn(v1));
                    float h8 = __bfloat162float(__float2bfloat16_rn(v8));
                    float h9 = __bfloat162float(__float2bfloat16_rn(v9));
                    hw[2 * tt] = packb(h0, h1);
                    hw[2 * tt + 1] = packb(h8, h9);
                    lw[2 * tt] = packb(v0 - h0, v1 - h1);
                    lw[2 * tt + 1] = packb(v8 - h8, v9 - h9);
                }
                *(uint4*)(smem + wbase + (0 ^ wswz)) = make_uint4(hw[0], hw[1], hw[2], hw[3]);
                *(uint4*)(smem + wbase + (16 ^ wswz)) = make_uint4(hw[4], hw[5], hw[6], hw[7]);
                *(uint4*)(smem + SM_AL + wbase + (0 ^ wswz)) = make_uint4(lw[0], lw[1], lw[2], lw[3]);
                *(uint4*)(smem + SM_AL + wbase + (16 ^ wswz)) = make_uint4(lw[4], lw[5], lw[6], lw[7]);
            }
            // ---- writer: X (BN + ReLU, split hi/lo) ----
            {
                const int kb = kc * 32 + wh * 16;
                float v[16];
#pragma unroll
                for (int q = 0; q < 4; q++) {
                    v[q * 4 + 0] = px[q].x; v[q * 4 + 1] = px[q].y;
                    v[q * 4 + 2] = px[q].z; v[q * 4 + 3] = px[q].w;
                }
#pragma unroll
                for (int e = 0; e < 16; e++)
                    v[e] = fmaxf(fmaf(sc_s[kb + e], v[e], sh_s[kb + e]), 0.f);
                uint32_t hw[8], lw[8];
#pragma unroll
                for (int tt = 0; tt < 4; tt++) {
                    float v0 = v[2 * tt], v1 = v[2 * tt + 1];
                    float v8 = v[2 * tt + 8], v9 = v[2 * tt + 9];
                    float h0 = __bfloat162float(__float2bfloat16_rn(v0));
                    float h1 = __bfloat162float(__float2bfloat16_rn(v1));
                    float h8 = __bfloat162float(__float2bfloat16_rn(v8));
                    float h9 = __bfloat162float(__float2bfloat16_rn(v9));
                    hw[2 * tt] = packb(h0, h1);
                    hw[2 * tt + 1] = packb(h8, h9);
                    lw[2 * tt] = packb(v0 - h0, v1 - h1);
                    lw[2 * tt + 1] = packb(v8 - h8, v9 - h9);
                }
                *(uint4*)(smem + SM_XH + wbase + (0 ^ wswz)) = make_uint4(hw[0], hw[1], hw[2], hw[3]);
                *(uint4*)(smem + SM_XH + wbase + (16 ^ wswz)) = make_uint4(hw[4], hw[5], hw[6], hw[7]);
                *(uint4*)(smem + SM_XL + wbase + (0 ^ wswz)) = make_uint4(lw[0], lw[1], lw[2], lw[3]);
                *(uint4*)(smem + SM_XL + wbase + (16 ^ wswz)) = make_uint4(lw[4], lw[5], lw[6], lw[7]);
            }
            __syncthreads();
            if (kc + 1 < nkc) {  // prefetch next chunk during compute
#pragma unroll
                for (int q = 0; q < 4; q++) {
                    pa[q] = *(const float4*)(Wm + (kc + 1) * 32 + q * 4);
                    px[q] = *(const float4*)(Xc + (kc + 1) * 32 + q * 4);
                }
            }
#pragma unroll
            for (int kk = 0; kk < 2; kk++) {
                const char* base = smem + kk * 4096;
                uint32_t ah[2][4], al[2][4];
#pragma unroll
                for (int i = 0; i < 2; i++) {
                    const int r1 = m0 + i * 16 + g;
                    const int r2 = r1 + 8;
                    const uint32_t o1 = (uint32_t)r1 * 32 + ((t * 8) ^ (((r1 >> 2) & 1) * 16));
                    const uint32_t o2 = (uint32_t)r2 * 32 + ((t * 8) ^ (((r2 >> 2) & 1) * 16));
                    uint2 h1 = *(const uint2*)(base + o1);
                    uint2 h2 = *(const uint2*)(base + o2);
                    ah[i][0] = h1.x; ah[i][1] = h2.x; ah[i][2] = h1.y; ah[i][3] = h2.y;
                    uint2 l1 = *(const uint2*)(base + SM_AL + o1);
                    uint2 l2 = *(const uint2*)(base + SM_AL + o2);
                    al[i][0] = l1.x; al[i][1] = l2.x; al[i][2] = l1.y; al[i][3] = l2.y;
                }
#pragma unroll
                for (int j = 0; j < 8; j++) {
                    const int rb = n0 + j * 8 + g;
                    const uint32_t ob = (uint32_t)rb * 32 + ((t * 8) ^ (((rb >> 2) & 1) * 16));
                    uint2 bh = *(const uint2*)(base + SM_XH + ob);
                    uint2 bl = *(const uint2*)(base + SM_XL + ob);
#pragma unroll
                    for (int i = 0; i < 2; i++) {
                        mma16(c[i][j], ah[i], bl.x, bl.y);
                        mma16(c[i][j], al[i], bh.x, bh.y);
                        mma16(c[i][j], ah[i], bh.x, bh.y);
                    }
                }
            }
        }

        // ---- epilogue: bias, stats (+max), optional transposed store ----
#pragma unroll
        for (int i = 0; i < 2; i++) {
            const int chA = mc * 128 + m0 + i * 16 + g;
            const int chB = chA + 8;
            const float bvA = COLBIAS ? colbias[bb * Mtot + chA] : bias[chA];
            const float bvB = COLBIAS ? colbias[bb * Mtot + chB] : bias[chB];
            float sA = 0.f, qA = 0.f, sB = 0.f, qB = 0.f;
            float mA = -3.4e38f, mB = -3.4e38f;
#pragma unroll
            for (int j = 0; j < 8; j++) {
                c[i][j][0] += bvA; c[i][j][1] += bvA;
                c[i][j][2] += bvB; c[i][j][3] += bvB;
                sA += c[i][j][0] + c[i][j][1];
                qA = fmaf(c[i][j][0], c[i][j][0], qA);
                qA = fmaf(c[i][j][1], c[i][j][1], qA);
                sB += c[i][j][2] + c[i][j][3];
                qB = fmaf(c[i][j][2], c[i][j][2], qB);
                qB = fmaf(c[i][j][3], c[i][j][3], qB);
                if (DOMAX) {
                    mA = fmaxf(mA, fmaxf(c[i][j][0], c[i][j][1]));
                    mB = fmaxf(mB, fmaxf(c[i][j][2], c[i][j][3]));
                }
            }
#pragma unroll
            for (int o = 1; o <= 2; o <<= 1) {
                sA += __shfl_xor_sync(0xffffffffu, sA, o);
                qA += __shfl_xor_sync(0xffffffffu, qA, o);
                sB += __shfl_xor_sync(0xffffffffu, sB, o);
                qB += __shfl_xor_sync(0xffffffffu, qB, o);
                if (DOMAX) {
                    mA = fmaxf(mA, __shfl_xor_sync(0xffffffffu, mA, o));
                    mB = fmaxf(mB, __shfl_xor_sync(0xffffffffu, mB, o));
                }
            }
            if (t == 0) {
                atomicAdd(&d_sum[statoff + chA], sA);
                atomicAdd(&d_sq[statoff + chA], qA);
                atomicAdd(&d_sum[statoff + chB], sB);
                atomicAdd(&d_sq[statoff + chB], qB);
                if (DOMAX) {
                    unsigned uA = __float_as_uint(mA);
                    uA = (uA >> 31) ? ~uA : (uA | 0x80000000u);
                    atomicMax(&d_gmax[bb * Mtot + chA], uA);
                    unsigned uB = __float_as_uint(mB);
                    uB = (uB >> 31) ? ~uB : (uB | 0x80000000u);
                    atomicMax(&d_gmax[bb * Mtot + chB], uB);
                }
            }
        }

        if (STORE) {
#pragma unroll
            for (int h = 0; h < 2; h++) {
                __syncthreads();
                if ((wid >> 2) == h) {
#pragma unroll
                    for (int i = 0; i < 2; i++)
#pragma unroll
                        for (int j = 0; j < 8; j++) {
                            const int lc = j * 8 + t * 2;
                            const int chl = m0 + i * 16 + g;
                            S[lc * 132 + chl] = c[i][j][0];
                            S[(lc + 1) * 132 + chl] = c[i][j][1];
                            S[lc * 132 + chl + 8] = c[i][j][2];
                            S[(lc + 1) * 132 + chl + 8] = c[i][j][3];
                        }
                }
                __syncthreads();
                const int lcol = tid >> 2;
                const int cg2 = (tid & 3) * 32;
                float* yp = Y + (size_t)(col0 + h * 64 + lcol) * Mtot + mc * 128 + cg2;
                const float* sp = S + lcol * 132 + cg2;
#pragma unroll
                for (int q = 0; q < 8; q++)
                    *(float4*)(yp + q * 4) = *(const float4*)(sp + q * 4);
            }
        }
    }
}

// decode max, apply conv3 BN affine
__global__ void gbn_kernel() {
    int i = blockIdx.x * 256 + threadIdx.x;
    unsigned u = d_gmax[i];
    float f = (u >> 31) ? __uint_as_float(u & 0x7FFFFFFFu) : __uint_as_float(~u);
    int c = i & 1023;
    d_gbn[i] = fmaf(d_scale[OFF3 + c], f, d_shift[OFF3 + c]);
}

// hvec[b][oc] = h_w1[oc, :1024] @ g_bn[b] + h_b1[oc]
__global__ void hvec_kernel(const float* __restrict__ w1, const float* __restrict__ b1) {
    int bbk = blockIdx.x;
    int oc = blockIdx.y * 128 + threadIdx.x;
    __shared__ float gb[1024];
    for (int i = threadIdx.x; i < 1024; i += 128) gb[i] = d_gbn[bbk * 1024 + i];
    __syncthreads();
    float a = b1[oc];
    const float* wr = w1 + (size_t)oc * 1088;
#pragma unroll 4
    for (int k = 0; k < 1024; k++) a = fmaf(wr[k], gb[k], a);
    d_hvec[bbk * 512 + oc] = a;
}

// h4: 128 -> 1, warp per column ([col][128] layout), weights into d_out
__global__ void h4_kernel(const float* __restrict__ w4, const float* __restrict__ b4,
                          float* __restrict__ out) {
    __shared__ float ws[128], scs[128], shs[128];
    __shared__ int vcnt;
    int tid = threadIdx.x;
    if (tid < 128) {
        ws[tid] = w4[tid];
        scs[tid] = d_scale[OFFH3 + tid];
        shs[tid] = d_shift[OFFH3 + tid];
    }
    if (tid == 0) vcnt = 0;
    __syncthreads();
    int wid = tid >> 5, lid = tid & 31;
    int col = blockIdx.x * 8 + wid;
    const float* src = d_rawh3 + (size_t)col * 128;
    float a = 0.f;
#pragma unroll
    for (int c = 0; c < 4; c++) {
        int k = c * 32 + lid;
        float v = src[k];
        a = fmaf(ws[k], fmaxf(fmaf(scs[k], v, shs[k]), 0.f), a);
    }
#pragma unroll
    for (int o = 16; o >= 1; o >>= 1) a += __shfl_xor_sync(0xffffffffu, a, o);
    if (lid == 0) {
        float wv = 1.f + a + __ldg(b4);
        out[96 + col] = wv;
        if (wv > 1e-4f) atomicAdd(&vcnt, 1);
    }
    __syncthreads();
    if (tid == 0) atomicAdd(&d_nv[(blockIdx.x * 8) >> 11], vcnt);
}

// per-batch weighted 3x3 normal equations + Cholesky
__global__ void solve_kernel(const float* __restrict__ pts, float* __restrict__ out) {
    int bbk = blockIdx.x;
    const float* w = out + 96 + bbk * NPTS;
    const float* px = pts + (size_t)bbk * 3 * NPTS;
    bool usew = d_nv[bbk] > 3;
    float acc[9];
#pragma unroll
    for (int k = 0; k < 9; k++) acc[k] = 0.f;
    for (int n = threadIdx.x; n < NPTS; n += 256) {
        float wv = w[n];
        float we = usew ? ((wv > 1e-4f) ? wv : 0.f) : 1.f;
        float x = px[n], y = px[NPTS + n], z = px[2 * NPTS + n];
        acc[0] = fmaf(we * x, x, acc[0]);
        acc[1] = fmaf(we * x, y, acc[1]);
        acc[2] += we * x;
        acc[3] = fmaf(we * y, y, acc[3]);
        acc[4] += we * y;
        acc[5] += we;
        acc[6] = fmaf(we * x, z, acc[6]);
        acc[7] = fmaf(we * y, z, acc[7]);
        acc[8] = fmaf(we, z, acc[8]);
    }
#pragma unroll
    for (int k = 0; k < 9; k++)
#pragma unroll
        for (int o = 16; o >= 1; o >>= 1) acc[k] += __shfl_xor_sync(0xffffffffu, acc[k], o);
    __shared__ float red[8][9];
    int wid = threadIdx.x >> 5, lane = threadIdx.x & 31;
    if (lane == 0)
        for (int k = 0; k < 9; k++) red[wid][k] = acc[k];
    __syncthreads();
    if (threadIdx.x == 0) {
        float a[9];
        for (int k = 0; k < 9; k++) {
            float s = 0.f;
            for (int i = 0; i < 8; i++) s += red[i][k];
            a[k] = s;
        }
        float L11 = sqrtf(a[0]);
        float L21 = a[1] / L11, L31 = a[2] / L11;
        float L22 = sqrtf(a[3] - L21 * L21);
        float L32 = (a[4] - L31 * L21) / L22;
        float L33 = sqrtf(a[5] - L31 * L31 - L32 * L32);
        float y1 = a[6] / L11;
        float y2 = (a[7] - L21 * y1) / L22;
        float y3 = (a[8] - L31 * y1 - L32 * y2) / L33;
        float be3 = y3 / L33;
        float be2 = (y2 - L32 * be3) / L22;
        float be1 = (y1 - L21 * be2 - L31 * be3) / L11;
        out[bbk * 3 + 0] = be1;
        out[bbk * 3 + 1] = be2;
        out[bbk * 3 + 2] = be3;
    }
}

// ================= launch =================
extern "C" void kernel_launch(void* const* d_in, const int* in_sizes, int n_in,
                              void* d_out, int out_size) {
    const float* pts = (const float*)d_in[0];
    const float* e_w1 = (const float*)d_in[1];
    const float* e_b1 = (const float*)d_in[2];
    const float* e_g1 = (const float*)d_in[3];
    const float* e_be1 = (const float*)d_in[4];
    const float* e_w2 = (const float*)d_in[5];
    const float* e_b2 = (const float*)d_in[6];
    const float* e_g2 = (const float*)d_in[7];
    const float* e_be2 = (const float*)d_in[8];
    const float* e_w3 = (const float*)d_in[9];
    const float* e_b3 = (const float*)d_in[10];
    const float* e_g3 = (const float*)d_in[11];
    const float* e_be3 = (const float*)d_in[12];
    const float* h_w1 = (const float*)d_in[13];
    const float* h_b1 = (const float*)d_in[14];
    const float* h_g1 = (const float*)d_in[15];
    const float* h_be1 = (const float*)d_in[16];
    const float* h_w2 = (const float*)d_in[17];
    const float* h_b2 = (const float*)d_in[18];
    const float* h_g2 = (const float*)d_in[19];
    const float* h_be2 = (const float*)d_in[20];
    const float* h_w3 = (const float*)d_in[21];
    const float* h_b3 = (const float*)d_in[22];
    const float* h_g3 = (const float*)d_in[23];
    const float* h_be3 = (const float*)d_in[24];
    const float* h_w4 = (const float*)d_in[25];
    const float* h_b4 = (const float*)d_in[26];
    float* out = (float*)d_out;

    float *p_raw1, *p_raw2, *p_rawh1, *p_rawh2, *p_rawh3, *p_hvec;
    cudaGetSymbolAddress((void**)&p_raw1, d_raw1);
    cudaGetSymbolAddress((void**)&p_raw2, d_raw2);
    cudaGetSymbolAddress((void**)&p_rawh1, d_rawh1);
    cudaGetSymbolAddress((void**)&p_rawh2, d_rawh2);
    cudaGetSymbolAddress((void**)&p_rawh3, d_rawh3);
    cudaGetSymbolAddress((void**)&p_hvec, d_hvec);

    zero_kernel<<<128, 256>>>();
    conv1_kernel<<<256, 256>>>(pts, e_w1, e_b1);
    finalize_kernel<<<1, 128>>>(64, OFF1, e_g1, e_be1);
    // conv2: 128 x 65536 x 64
    mma_kernel<true, false, false><<<512, 256>>>(e_w2, 64, 0, e_b2, p_raw1, 64, OFF1,
                                                 p_raw2, OFF2, 128, nullptr);
    finalize_kernel<<<1, 128>>>(128, OFF2, e_g2, e_be2);
    // conv3: 1024 x 65536 x 128 (stats + max only, no store)
    mma_kernel<false, true, false><<<512, 256>>>(e_w3, 128, 0, e_b3, p_raw2, 128, OFF2,
                                                 nullptr, OFF3, 1024, nullptr);
    finalize_kernel<<<8, 128>>>(1024, OFF3, e_g3, e_be3);
    gbn_kernel<<<128, 256>>>();
    hvec_kernel<<<dim3(32, 4), 128>>>(h_w1, h_b1);
    // h1 (pointfeat part): 512 x 65536 x 64, per-batch colbias
    mma_kernel<true, false, true><<<512, 256>>>(h_w1, 1088, 1024, h_b1, p_raw1, 64, OFF1,
                                                p_rawh1, OFFH1, 512, p_hvec);
    finalize_kernel<<<4, 128>>>(512, OFFH1, h_g1, h_be1);
    // h2: 256 x 65536 x 512
    mma_kernel<true, false, false><<<512, 256>>>(h_w2, 512, 0, h_b2, p_rawh1, 512, OFFH1,
                                                 p_rawh2, OFFH2, 256, nullptr);
    finalize_kernel<<<2, 128>>>(256, OFFH2, h_g2, h_be2);
    // h3: 128 x 65536 x 256
    mma_kernel<true, false, false><<<512, 256>>>(h_w3, 256, 0, h_b3, p_rawh2, 256, OFFH2,
                                                 p_rawh3, OFFH3, 128, nullptr);
    finalize_kernel<<<1, 128>>>(128, OFFH3, h_g3, h_be3);
    h4_kernel<<<8192, 256>>>(h_w4, h_b4, out);
    solve_kernel<<<32, 256>>>(pts, out);
}

// round 6
// speedup vs baseline: 1.8254x; 1.4471x over previous
#include <cuda_runtime.h>
#include <cuda_bf16.h>
#include <cstdint>

#define NCOL 65536
#define NB 32
#define NPTS 2048

#define OFF1 0
#define OFF2 64
#define OFF3 192
#define OFFH1 1216
#define OFFH2 1728
#define OFFH3 1984
#define NSTAT 2112

// weight-plane byte offsets (Mtot*Cin*4 bytes each: bf16 hi+lo fragment layout)
#define WOFF_C2 0
#define WOFF_C3 32768
#define WOFF_H1 557056
#define WOFF_H2 688128
#define WOFF_H3 1212416
#define WPL_TOTAL 1343488

// ---- scratch ----
__device__ float d_raw1[(size_t)NCOL * 64];
__device__ float d_raw2[(size_t)NCOL * 128];
__device__ float d_rawh1[(size_t)NCOL * 512];
__device__ float d_rawh2[(size_t)NCOL * 256];
__device__ float d_rawh3[(size_t)NCOL * 128];
__device__ __align__(16) char d_wpl[WPL_TOTAL];
__device__ float d_sum[NSTAT];
__device__ float d_sq[NSTAT];
__device__ float d_scale[NSTAT];
__device__ float d_shift[NSTAT];
__device__ unsigned d_gmax[NB * 1024];
__device__ float d_gbn[NB * 1024];
__device__ float d_hvec[NB * 512];
__device__ int d_nv[NB];

__device__ __forceinline__ uint32_t smem_u32(const void* p) {
    uint32_t a;
    asm("{ .reg .u64 t; cvta.to.shared.u64 t, %1; cvt.u32.u64 %0, t; }" : "=r"(a) : "l"(p));
    return a;
}
#define CP16(sa, ga) \
    asm volatile("cp.async.cg.shared.global [%0], [%1], 16;" ::"r"(sa), "l"(ga) : "memory")
#define CPC asm volatile("cp.async.commit_group;" ::: "memory")
#define CPW2 asm volatile("cp.async.wait_group 2;" ::: "memory")

__device__ __forceinline__ void mma16(float c[4], const uint32_t a[4], uint32_t b0,
                                      uint32_t b1) {
    asm volatile(
        "mma.sync.aligned.m16n8k16.row.col.f32.bf16.bf16.f32 "
        "{%0,%1,%2,%3}, {%4,%5,%6,%7}, {%8,%9}, {%0,%1,%2,%3};"
        : "+f"(c[0]), "+f"(c[1]), "+f"(c[2]), "+f"(c[3])
        : "r"(a[0]), "r"(a[1]), "r"(a[2]), "r"(a[3]), "r"(b0), "r"(b1));
}
__device__ __forceinline__ uint32_t packb(float lo_e, float hi_e) {
    __nv_bfloat162 h;
    h.x = __float2bfloat16_rn(lo_e);
    h.y = __float2bfloat16_rn(hi_e);
    return *(uint32_t*)&h;
}
// split 16 values (fragment order) and write hi/lo uint4 pairs
__device__ __forceinline__ void split16_store(const float v[16], char* dhi, char* dlo,
                                              uint32_t swz) {
    uint32_t hw[8], lw[8];
#pragma unroll
    for (int tt = 0; tt < 4; tt++) {
        float v0 = v[2 * tt], v1 = v[2 * tt + 1];
        float v8 = v[2 * tt + 8], v9 = v[2 * tt + 9];
        float h0 = __bfloat162float(__float2bfloat16_rn(v0));
        float h1 = __bfloat162float(__float2bfloat16_rn(v1));
        float h8 = __bfloat162float(__float2bfloat16_rn(v8));
        float h9 = __bfloat162float(__float2bfloat16_rn(v9));
        hw[2 * tt] = packb(h0, h1);
        hw[2 * tt + 1] = packb(h8, h9);
        lw[2 * tt] = packb(v0 - h0, v1 - h1);
        lw[2 * tt + 1] = packb(v8 - h8, v9 - h9);
    }
    *(uint4*)(dhi + (0 ^ swz)) = make_uint4(hw[0], hw[1], hw[2], hw[3]);
    *(uint4*)(dhi + (16 ^ swz)) = make_uint4(hw[4], hw[5], hw[6], hw[7]);
    *(uint4*)(dlo + (0 ^ swz)) = make_uint4(lw[0], lw[1], lw[2], lw[3]);
    *(uint4*)(dlo + (16 ^ swz)) = make_uint4(lw[4], lw[5], lw[6], lw[7]);
}

// ================= small kernels =================
__global__ void zero_kernel() {
    int i = blockIdx.x * 256 + threadIdx.x;
    if (i < NSTAT) { d_sum[i] = 0.f; d_sq[i] = 0.f; }
    if (i < NB * 1024) d_gmax[i] = 0u;
    if (i < NB) d_nv[i] = 0;
}

// precompute weight bf16 hi/lo planes, layout [mc][k16][pl][128 rows][32B] (+swizzle)
__global__ void wsplit_kernel(const float* __restrict__ W, int lda, int woff, int Cin,
                              int total, char* __restrict__ dst) {
    int idx = blockIdx.x * 256 + threadIdx.x;
    if (idx >= total) return;
    const int TK = Cin >> 4;
    const int m = idx / TK, k16 = idx % TK;
    const float* src = W + (size_t)m * lda + woff + k16 * 16;
    float v[16];
#pragma unroll
    for (int q = 0; q < 4; q++) {
        float4 f = *(const float4*)(src + q * 4);
        v[q * 4 + 0] = f.x; v[q * 4 + 1] = f.y; v[q * 4 + 2] = f.z; v[q * 4 + 3] = f.w;
    }
    const int row = m & 127;
    const uint32_t swz = ((row >> 2) & 1) * 16;
    char* base = dst + (size_t)(((m >> 7) * TK + k16) * 2) * 4096 + row * 32;
    split16_store(v, base, base + 4096, swz);
}

// conv1: 3 -> 64, transposed out [col][64], fused stats
__global__ void conv1_kernel(const float* __restrict__ pts,
                             const float* __restrict__ w,
                             const float* __restrict__ b) {
    __shared__ float ws[192], bs[64], bsum[64], bsq[64];
    int tid = threadIdx.x;
    if (tid < 192) ws[tid] = w[tid];
    if (tid < 64) { bs[tid] = b[tid]; bsum[tid] = 0.f; bsq[tid] = 0.f; }
    __syncthreads();
    int wid = tid >> 5, lid = tid & 31;
    int colbase = (blockIdx.x * 8 + wid) * 32;
    int bb = colbase >> 11, n = colbase & 2047;
    const float* p = pts + (size_t)bb * 3 * NPTS + n + lid;
    float p0 = p[0], p1 = p[NPTS], p2 = p[2 * NPTS];
    float wa0 = ws[lid * 3], wa1 = ws[lid * 3 + 1], wa2 = ws[lid * 3 + 2];
    float wb0 = ws[(lid + 32) * 3], wb1 = ws[(lid + 32) * 3 + 1], wb2 = ws[(lid + 32) * 3 + 2];
    float ba = bs[lid], bbv = bs[lid + 32];
    float sa = 0.f, qa = 0.f, sb = 0.f, qb = 0.f;
#pragma unroll 8
    for (int c = 0; c < 32; c++) {
        float x = __shfl_sync(0xffffffffu, p0, c);
        float y = __shfl_sync(0xffffffffu, p1, c);
        float z = __shfl_sync(0xffffffffu, p2, c);
        float va = fmaf(wa0, x, fmaf(wa1, y, fmaf(wa2, z, ba)));
        float vb = fmaf(wb0, x, fmaf(wb1, y, fmaf(wb2, z, bbv)));
        d_raw1[(size_t)(colbase + c) * 64 + lid] = va;
        d_raw1[(size_t)(colbase + c) * 64 + 32 + lid] = vb;
        sa += va; qa = fmaf(va, va, qa);
        sb += vb; qb = fmaf(vb, vb, qb);
    }
    atomicAdd(&bsum[lid], sa); atomicAdd(&bsq[lid], qa);
    atomicAdd(&bsum[32 + lid], sb); atomicAdd(&bsq[32 + lid], qb);
    __syncthreads();
    if (tid < 64) {
        atomicAdd(&d_sum[OFF1 + tid], bsum[tid]);
        atomicAdd(&d_sq[OFF1 + tid], bsq[tid]);
    }
}

__global__ void finalize_kernel(int C, int off, const float* __restrict__ g,
                                const float* __restrict__ be) {
    int c = blockIdx.x * 128 + threadIdx.x;
    if (c >= C) return;
    float m = d_sum[off + c] * (1.0f / NCOL);
    float v = d_sq[off + c] * (1.0f / NCOL) - m * m;
    float sc = g[c] * rsqrtf(v + 1e-5f);
    d_scale[off + c] = sc;
    d_shift[off + c] = fmaf(-m, sc, be[c]);
}

// ================= pipelined bf16x3 HMMA GEMM =================
// XRES: X planes resident in smem @0 (TK*8192 B), A ring @AOFF (4 x 8192).
// streaming: X 2-stage ring @0 (2 x 8192), A ring @16384.
// S (32x132 floats, 16896 B) overlays the A ring during epilogue.
template <bool XRES, bool STORE, bool DOMAX, bool COLBIAS>
__global__ void __launch_bounds__(256, 2) mma_kernel(
    const char* __restrict__ wpl, const float* __restrict__ bias,
    const float* __restrict__ Xraw, int Cin, int actoff,
    float* __restrict__ Y, int statoff, int Mtot,
    const float* __restrict__ colbias) {
    extern __shared__ __align__(16) char smem[];
    const int tid = threadIdx.x;
    const int wid = tid >> 5, lane = tid & 31;
    const int g = lane >> 2, t4 = lane & 3;
    const int m0 = (wid & 3) * 32;
    const int n0 = (wid >> 2) * 64;
    const int col0 = blockIdx.x * 128;
    const int bb = col0 >> 11;
    const int TK = Cin >> 4, MC = Mtot >> 7;
    const int AOFF = XRES ? (TK * 8192) : 16384;
    const uint32_t aB = smem_u32(smem) + AOFF;
    float* S = (float*)(smem + AOFF);

    const int row = tid & 127;
    const int grp = tid >> 7;
    const uint32_t swzr = ((row >> 2) & 1) * 16;

    if (XRES) {  // convert ALL X once into resident planes
        for (int k16 = grp; k16 < TK; k16 += 2) {
            const float* src = Xraw + (size_t)(col0 + row) * Cin + k16 * 16;
            float v[16];
#pragma unroll
            for (int q = 0; q < 4; q++) {
                float4 f = *(const float4*)(src + q * 4);
                float4 sc = *(const float4*)(d_scale + actoff + k16 * 16 + q * 4);
                float4 sh = *(const float4*)(d_shift + actoff + k16 * 16 + q * 4);
                v[q * 4 + 0] = fmaxf(fmaf(sc.x, f.x, sh.x), 0.f);
                v[q * 4 + 1] = fmaxf(fmaf(sc.y, f.y, sh.y), 0.f);
                v[q * 4 + 2] = fmaxf(fmaf(sc.z, f.z, sh.z), 0.f);
                v[q * 4 + 3] = fmaxf(fmaf(sc.w, f.w, sh.w), 0.f);
            }
            char* dh = smem + k16 * 8192 + row * 32;
            split16_store(v, dh, dh + 4096, swzr);
        }
    }

    const float* xsrc = Xraw + (size_t)(col0 + row) * Cin;
    const int xo1 = grp * 4, xo2 = grp * 4 + 8;

    for (int mc = 0; mc < MC; mc++) {
        __syncthreads();  // covers XRES phase0 / prev epilogue S reads
        float c[2][8][4];
#pragma unroll
        for (int i = 0; i < 2; i++)
#pragma unroll
            for (int j = 0; j < 8; j++)
#pragma unroll
                for (int k = 0; k < 4; k++) c[i][j][k] = 0.f;

        const char* gA = wpl + (size_t)mc * TK * 8192;
        // preamble: stages 0,1
        {
            uint32_t s0 = aB + tid * 32;
            CP16(s0, gA + tid * 32); CP16(s0 + 16, gA + tid * 32 + 16); CPC;
            uint32_t s1 = aB + 8192 + tid * 32;
            CP16(s1, gA + 8192 + tid * 32); CP16(s1 + 16, gA + 8192 + tid * 32 + 16); CPC;
        }
        float4 px0, px1;
        if (!XRES) { px0 = *(const float4*)(xsrc + xo1); px1 = *(const float4*)(xsrc + xo2); }

        for (int t = 0; t < TK; t++) {
            if (!XRES) {  // BN+relu+split+STS this k16 into X ring
                float v[16];
                float4 sc0 = *(const float4*)(d_scale + actoff + t * 16 + xo1);
                float4 sh0 = *(const float4*)(d_shift + actoff + t * 16 + xo1);
                float4 sc1 = *(const float4*)(d_scale + actoff + t * 16 + xo2);
                float4 sh1 = *(const float4*)(d_shift + actoff + t * 16 + xo2);
                v[0] = fmaxf(fmaf(sc0.x, px0.x, sh0.x), 0.f);
                v[1] = fmaxf(fmaf(sc0.y, px0.y, sh0.y), 0.f);
                v[2] = fmaxf(fmaf(sc0.z, px0.z, sh0.z), 0.f);
                v[3] = fmaxf(fmaf(sc0.w, px0.w, sh0.w), 0.f);
                v[4] = fmaxf(fmaf(sc1.x, px1.x, sh1.x), 0.f);
                v[5] = fmaxf(fmaf(sc1.y, px1.y, sh1.y), 0.f);
                v[6] = fmaxf(fmaf(sc1.z, px1.z, sh1.z), 0.f);
                v[7] = fmaxf(fmaf(sc1.w, px1.w, sh1.w), 0.f);
                // pack 4 hi + 4 lo (slots for this half): (v0,v1),(v4,v5),(v2,v3),(v6,v7)
                uint32_t hw[4], lw[4];
                float h0 = __bfloat162float(__float2bfloat16_rn(v[0]));
                float h1 = __bfloat162float(__float2bfloat16_rn(v[1]));
                float h4 = __bfloat162float(__float2bfloat16_rn(v[4]));
                float h5 = __bfloat162float(__float2bfloat16_rn(v[5]));
                float h2 = __bfloat162float(__float2bfloat16_rn(v[2]));
                float h3 = __bfloat162float(__float2bfloat16_rn(v[3]));
                float h6 = __bfloat162float(__float2bfloat16_rn(v[6]));
                float h7 = __bfloat162float(__float2bfloat16_rn(v[7]));
                hw[0] = packb(h0, h1); hw[1] = packb(h4, h5);
                hw[2] = packb(h2, h3); hw[3] = packb(h6, h7);
                lw[0] = packb(v[0] - h0, v[1] - h1); lw[1] = packb(v[4] - h4, v[5] - h5);
                lw[2] = packb(v[2] - h2, v[3] - h3); lw[3] = packb(v[6] - h6, v[7] - h7);
                char* dx = smem + (t & 1) * 8192 + row * 32;
                *(uint4*)(dx + ((grp * 16) ^ swzr)) = make_uint4(hw[0], hw[1], hw[2], hw[3]);
                *(uint4*)(dx + 4096 + ((grp * 16) ^ swzr)) = make_uint4(lw[0], lw[1], lw[2], lw[3]);
            }
            if (t + 2 < TK) {  // stage A(t+2)
                uint32_t sd = aB + ((t + 2) & 3) * 8192 + tid * 32;
                const char* gs = gA + (size_t)(t + 2) * 8192 + tid * 32;
                CP16(sd, gs); CP16(sd + 16, gs + 16);
            }
            CPC;  // (possibly empty group keeps wait count uniform)
            if (!XRES && t + 1 < TK) {
                px0 = *(const float4*)(xsrc + (t + 1) * 16 + xo1);
                px1 = *(const float4*)(xsrc + (t + 1) * 16 + xo2);
            }
            CPW2;
            __syncthreads();
            // ---- MMA on k16 t ----
            const char* ab = smem + AOFF + (t & 3) * 8192;
            const char* xb = XRES ? (smem + t * 8192) : (smem + (t & 1) * 8192);
            uint32_t ah[2][4], al[2][4];
#pragma unroll
            for (int i = 0; i < 2; i++) {
                const int r1 = m0 + i * 16 + g, r2 = r1 + 8;
                const uint32_t o1 = (uint32_t)r1 * 32 + ((t4 * 8) ^ (((r1 >> 2) & 1) * 16));
                const uint32_t o2 = (uint32_t)r2 * 32 + ((t4 * 8) ^ (((r2 >> 2) & 1) * 16));
                uint2 h1 = *(const uint2*)(ab + o1);
                uint2 h2 = *(const uint2*)(ab + o2);
                ah[i][0] = h1.x; ah[i][1] = h2.x; ah[i][2] = h1.y; ah[i][3] = h2.y;
                uint2 l1 = *(const uint2*)(ab + 4096 + o1);
                uint2 l2 = *(const uint2*)(ab + 4096 + o2);
                al[i][0] = l1.x; al[i][1] = l2.x; al[i][2] = l1.y; al[i][3] = l2.y;
            }
#pragma unroll
            for (int j = 0; j < 8; j++) {
                const int rb = n0 + j * 8 + g;
                const uint32_t ob = (uint32_t)rb * 32 + ((t4 * 8) ^ (((rb >> 2) & 1) * 16));
                uint2 bh = *(const uint2*)(xb + ob);
                uint2 bl = *(const uint2*)(xb + 4096 + ob);
#pragma unroll
                for (int i = 0; i < 2; i++) {
                    mma16(c[i][j], ah[i], bl.x, bl.y);
                    mma16(c[i][j], al[i], bh.x, bh.y);
                    mma16(c[i][j], ah[i], bh.x, bh.y);
                }
            }
        }

        // ---- epilogue: bias, stats (+max) ----
#pragma unroll
        for (int i = 0; i < 2; i++) {
            const int chA = mc * 128 + m0 + i * 16 + g;
            const int chB = chA + 8;
            const float bvA = COLBIAS ? colbias[bb * Mtot + chA] : bias[chA];
            const float bvB = COLBIAS ? colbias[bb * Mtot + chB] : bias[chB];
            float sA = 0.f, qA = 0.f, sB = 0.f, qB = 0.f;
            float mA = -3.4e38f, mB = -3.4e38f;
#pragma unroll
            for (int j = 0; j < 8; j++) {
                c[i][j][0] += bvA; c[i][j][1] += bvA;
                c[i][j][2] += bvB; c[i][j][3] += bvB;
                sA += c[i][j][0] + c[i][j][1];
                qA = fmaf(c[i][j][0], c[i][j][0], qA);
                qA = fmaf(c[i][j][1], c[i][j][1], qA);
                sB += c[i][j][2] + c[i][j][3];
                qB = fmaf(c[i][j][2], c[i][j][2], qB);
                qB = fmaf(c[i][j][3], c[i][j][3], qB);
                if (DOMAX) {
                    mA = fmaxf(mA, fmaxf(c[i][j][0], c[i][j][1]));
                    mB = fmaxf(mB, fmaxf(c[i][j][2], c[i][j][3]));
                }
            }
#pragma unroll
            for (int o = 1; o <= 2; o <<= 1) {
                sA += __shfl_xor_sync(0xffffffffu, sA, o);
                qA += __shfl_xor_sync(0xffffffffu, qA, o);
                sB += __shfl_xor_sync(0xffffffffu, sB, o);
                qB += __shfl_xor_sync(0xffffffffu, qB, o);
                if (DOMAX) {
                    mA = fmaxf(mA, __shfl_xor_sync(0xffffffffu, mA, o));
                    mB = fmaxf(mB, __shfl_xor_sync(0xffffffffu, mB, o));
                }
            }
            if (t4 == 0) {
                atomicAdd(&d_sum[statoff + chA], sA);
                atomicAdd(&d_sq[statoff + chA], qA);
                atomicAdd(&d_sum[statoff + chB], sB);
                atomicAdd(&d_sq[statoff + chB], qB);
                if (DOMAX) {
                    unsigned uA = __float_as_uint(mA);
                    uA = (uA >> 31) ? ~uA : (uA | 0x80000000u);
                    atomicMax(&d_gmax[bb * Mtot + chA], uA);
                    unsigned uB = __float_as_uint(mB);
                    uB = (uB >> 31) ? ~uB : (uB | 0x80000000u);
                    atomicMax(&d_gmax[bb * Mtot + chB], uB);
                }
            }
        }

        if (STORE) {  // 32-col slabs through S (overlays A ring; drained by now)
#pragma unroll
            for (int s = 0; s < 4; s++) {
                __syncthreads();
                if ((wid >> 2) == (s >> 1)) {
                    const int jb = (s & 1) * 4;
#pragma unroll
                    for (int i = 0; i < 2; i++)
#pragma unroll
                        for (int jj = 0; jj < 4; jj++) {
                            const int j = jb + jj;
                            const int lc = j * 8 + t4 * 2 - (s & 1) * 32;
                            const int chl = m0 + i * 16 + g;
                            S[lc * 132 + chl] = c[i][j][0];
                            S[(lc + 1) * 132 + chl] = c[i][j][1];
                            S[lc * 132 + chl + 8] = c[i][j][2];
                            S[(lc + 1) * 132 + chl + 8] = c[i][j][3];
                        }
                }
                __syncthreads();
                const int lcol = tid >> 3;
                const int cg2 = (tid & 7) * 16;
                float* yp = Y + (size_t)(col0 + s * 32 + lcol) * Mtot + mc * 128 + cg2;
                const float* sp = S + lcol * 132 + cg2;
#pragma unroll
                for (int q = 0; q < 4; q++)
                    *(float4*)(yp + q * 4) = *(const float4*)(sp + q * 4);
            }
        }
    }
}

// decode max, apply conv3 BN affine
__global__ void gbn_kernel() {
    int i = blockIdx.x * 256 + threadIdx.x;
    unsigned u = d_gmax[i];
    float f = (u >> 31) ? __uint_as_float(u & 0x7FFFFFFFu) : __uint_as_float(~u);
    int c = i & 1023;
    d_gbn[i] = fmaf(d_scale[OFF3 + c], f, d_shift[OFF3 + c]);
}

__global__ void hvec_kernel(const float* __restrict__ w1, const float* __restrict__ b1) {
    int bbk = blockIdx.x;
    int oc = blockIdx.y * 128 + threadIdx.x;
    __shared__ float gb[1024];
    for (int i = threadIdx.x; i < 1024; i += 128) gb[i] = d_gbn[bbk * 1024 + i];
    __syncthreads();
    float a = b1[oc];
    const float* wr = w1 + (size_t)oc * 1088;
#pragma unroll 4
    for (int k = 0; k < 1024; k++) a = fmaf(wr[k], gb[k], a);
    d_hvec[bbk * 512 + oc] = a;
}

__global__ void h4_kernel(const float* __restrict__ w4, const float* __restrict__ b4,
                          float* __restrict__ out) {
    __shared__ float ws[128], scs[128], shs[128];
    __shared__ int vcnt;
    int tid = threadIdx.x;
    if (tid < 128) {
        ws[tid] = w4[tid];
        scs[tid] = d_scale[OFFH3 + tid];
        shs[tid] = d_shift[OFFH3 + tid];
    }
    if (tid == 0) vcnt = 0;
    __syncthreads();
    int wid = tid >> 5, lid = tid & 31;
    int col = blockIdx.x * 8 + wid;
    const float* src = d_rawh3 + (size_t)col * 128;
    float a = 0.f;
#pragma unroll
    for (int c = 0; c < 4; c++) {
        int k = c * 32 + lid;
        float v = src[k];
        a = fmaf(ws[k], fmaxf(fmaf(scs[k], v, shs[k]), 0.f), a);
    }
#pragma unroll
    for (int o = 16; o >= 1; o >>= 1) a += __shfl_xor_sync(0xffffffffu, a, o);
    if (lid == 0) {
        float wv = 1.f + a + __ldg(b4);
        out[96 + col] = wv;
        if (wv > 1e-4f) atomicAdd(&vcnt, 1);
    }
    __syncthreads();
    if (tid == 0) atomicAdd(&d_nv[(blockIdx.x * 8) >> 11], vcnt);
}

__global__ void solve_kernel(const float* __restrict__ pts, float* __restrict__ out) {
    int bbk = blockIdx.x;
    const float* w = out + 96 + bbk * NPTS;
    const float* px = pts + (size_t)bbk * 3 * NPTS;
    bool usew = d_nv[bbk] > 3;
    float acc[9];
#pragma unroll
    for (int k = 0; k < 9; k++) acc[k] = 0.f;
    for (int n = threadIdx.x; n < NPTS; n += 256) {
        float wv = w[n];
        float we = usew ? ((wv > 1e-4f) ? wv : 0.f) : 1.f;
        float x = px[n], y = px[NPTS + n], z = px[2 * NPTS + n];
        acc[0] = fmaf(we * x, x, acc[0]);
        acc[1] = fmaf(we * x, y, acc[1]);
        acc[2] += we * x;
        acc[3] = fmaf(we * y, y, acc[3]);
        acc[4] += we * y;
        acc[5] += we;
        acc[6] = fmaf(we * x, z, acc[6]);
        acc[7] = fmaf(we * y, z, acc[7]);
        acc[8] = fmaf(we, z, acc[8]);
    }
#pragma unroll
    for (int k = 0; k < 9; k++)
#pragma unroll
        for (int o = 16; o >= 1; o >>= 1) acc[k] += __shfl_xor_sync(0xffffffffu, acc[k], o);
    __shared__ float red[8][9];
    int wid = threadIdx.x >> 5, lane = threadIdx.x & 31;
    if (lane == 0)
        for (int k = 0; k < 9; k++) red[wid][k] = acc[k];
    __syncthreads();
    if (threadIdx.x == 0) {
        float a[9];
        for (int k = 0; k < 9; k++) {
            float s = 0.f;
            for (int i = 0; i < 8; i++) s += red[i][k];
            a[k] = s;
        }
        float L11 = sqrtf(a[0]);
        float L21 = a[1] / L11, L31 = a[2] / L11;
        float L22 = sqrtf(a[3] - L21 * L21);
        float L32 = (a[4] - L31 * L21) / L22;
        float L33 = sqrtf(a[5] - L31 * L31 - L32 * L32);
        float y1 = a[6] / L11;
        float y2 = (a[7] - L21 * y1) / L22;
        float y3 = (a[8] - L31 * y1 - L32 * y2) / L33;
        float be3 = y3 / L33;
        float be2 = (y2 - L32 * be3) / L22;
        float be1 = (y1 - L21 * be2 - L31 * be3) / L11;
        out[bbk * 3 + 0] = be1;
        out[bbk * 3 + 1] = be2;
        out[bbk * 3 + 2] = be3;
    }
}

// ================= launch =================
extern "C" void kernel_launch(void* const* d_in, const int* in_sizes, int n_in,
                              void* d_out, int out_size) {
    const float* pts = (const float*)d_in[0];
    const float* e_w1 = (const float*)d_in[1];
    const float* e_b1 = (const float*)d_in[2];
    const float* e_g1 = (const float*)d_in[3];
    const float* e_be1 = (const float*)d_in[4];
    const float* e_w2 = (const float*)d_in[5];
    const float* e_b2 = (const float*)d_in[6];
    const float* e_g2 = (const float*)d_in[7];
    const float* e_be2 = (const float*)d_in[8];
    const float* e_w3 = (const float*)d_in[9];
    const float* e_b3 = (const float*)d_in[10];
    const float* e_g3 = (const float*)d_in[11];
    const float* e_be3 = (const float*)d_in[12];
    const float* h_w1 = (const float*)d_in[13];
    const float* h_b1 = (const float*)d_in[14];
    const float* h_g1 = (const float*)d_in[15];
    const float* h_be1 = (const float*)d_in[16];
    const float* h_w2 = (const float*)d_in[17];
    const float* h_b2 = (const float*)d_in[18];
    const float* h_g2 = (const float*)d_in[19];
    const float* h_be2 = (const float*)d_in[20];
    const float* h_w3 = (const float*)d_in[21];
    const float* h_b3 = (const float*)d_in[22];
    const float* h_g3 = (const float*)d_in[23];
    const float* h_be3 = (const float*)d_in[24];
    const float* h_w4 = (const float*)d_in[25];
    const float* h_b4 = (const float*)d_in[26];
    float* out = (float*)d_out;

    float *p_raw1, *p_raw2, *p_rawh1, *p_rawh2, *p_rawh3, *p_hvec;
    char* p_wpl;
    cudaGetSymbolAddress((void**)&p_raw1, d_raw1);
    cudaGetSymbolAddress((void**)&p_raw2, d_raw2);
    cudaGetSymbolAddress((void**)&p_rawh1, d_rawh1);
    cudaGetSymbolAddress((void**)&p_rawh2, d_rawh2);
    cudaGetSymbolAddress((void**)&p_rawh3, d_rawh3);
    cudaGetSymbolAddress((void**)&p_hvec, d_hvec);
    cudaGetSymbolAddress((void**)&p_wpl, d_wpl);

    cudaFuncSetAttribute(mma_kernel<true, true, false, false>,
                         cudaFuncAttributeMaxDynamicSharedMemorySize, 65536);
    cudaFuncSetAttribute(mma_kernel<true, false, true, false>,
                         cudaFuncAttributeMaxDynamicSharedMemorySize, 98304);
    cudaFuncSetAttribute(mma_kernel<true, true, false, true>,
                         cudaFuncAttributeMaxDynamicSharedMemorySize, 65536);
    cudaFuncSetAttribute(mma_kernel<false, true, false, false>,
                         cudaFuncAttributeMaxDynamicSharedMemorySize, 49152);

    zero_kernel<<<128, 256>>>();
    // precompute weight planes
    wsplit_kernel<<<2, 256>>>(e_w2, 64, 0, 64, 128 * 4, p_wpl + WOFF_C2);
    wsplit_kernel<<<32, 256>>>(e_w3, 128, 0, 128, 1024 * 8, p_wpl + WOFF_C3);
    wsplit_kernel<<<8, 256>>>(h_w1, 1088, 1024, 64, 512 * 4, p_wpl + WOFF_H1);
    wsplit_kernel<<<32, 256>>>(h_w2, 512, 0, 512, 256 * 32, p_wpl + WOFF_H2);
    wsplit_kernel<<<8, 256>>>(h_w3, 256, 0, 256, 128 * 16, p_wpl + WOFF_H3);

    conv1_kernel<<<256, 256>>>(pts, e_w1, e_b1);
    finalize_kernel<<<1, 128>>>(64, OFF1, e_g1, e_be1);
    // conv2: 128 x 65536 x 64 (XRES)
    mma_kernel<true, true, false, false><<<512, 256, 65536>>>(
        p_wpl + WOFF_C2, e_b2, p_raw1, 64, OFF1, p_raw2, OFF2, 128, nullptr);
    finalize_kernel<<<1, 128>>>(128, OFF2, e_g2, e_be2);
    // conv3: 1024 x 65536 x 128 (XRES, stats+max only)
    mma_kernel<true, false, true, false><<<512, 256, 98304>>>(
        p_wpl + WOFF_C3, e_b3, p_raw2, 128, OFF2, nullptr, OFF3, 1024, nullptr);
    finalize_kernel<<<8, 128>>>(1024, OFF3, e_g3, e_be3);
    gbn_kernel<<<128, 256>>>();
    hvec_kernel<<<dim3(32, 4), 128>>>(h_w1, h_b1);
    // h1 (pointfeat): 512 x 65536 x 64 (XRES, colbias)
    mma_kernel<true, true, false, true><<<512, 256, 65536>>>(
        p_wpl + WOFF_H1, h_b1, p_raw1, 64, OFF1, p_rawh1, OFFH1, 512, p_hvec);
    finalize_kernel<<<4, 128>>>(512, OFFH1, h_g1, h_be1);
    // h2: 256 x 65536 x 512 (streaming)
    mma_kernel<false, true, false, false><<<512, 256, 49152>>>(
        p_wpl + WOFF_H2, h_b2, p_rawh1, 512, OFFH1, p_rawh2, OFFH2, 256, nullptr);
    finalize_kernel<<<2, 128>>>(256, OFFH2, h_g2, h_be2);
    // h3: 128 x 65536 x 256 (streaming)
    mma_kernel<false, true, false, false><<<512, 256, 49152>>>(
        p_wpl + WOFF_H3, h_b3, p_rawh2, 256, OFFH2, p_rawh3, OFFH3, 128, nullptr);
    finalize_kernel<<<1, 128>>>(128, OFFH3, h_g3, h_be3);
    h4_kernel<<<8192, 256>>>(h_w4, h_b4, out);
    solve_kernel<<<32, 256>>>(pts, out);
}